// round 8
// baseline (speedup 1.0000x reference)
#include <cuda_runtime.h>
#include <cuda_fp16.h>

// ============================================================================
// AxialAttention — pure fp16 HMMA, fused attention+out-projection.
// R8: attn_out kernel (block = sequence): QKV smem tiles -> 8-head attention
//     (O overwrites Q in smem) -> streamed-Wout out-projection -> f32 out.
// ============================================================================

#define NTOK 131072          // 8*128*128 tokens

// ---- scratch (device globals: allocation-guard safe) ----
__device__ __half g_xh[NTOK * 256];
__device__ __half g_Qh[NTOK * 256];
__device__ __half g_Kh[NTOK * 256];
__device__ __half g_Vh[NTOK * 256];
__device__ __half g_Wh[8 * 65536];     // 8 mats, [n][k] 256x256

typedef unsigned long long ull;
typedef unsigned int       u32;
typedef unsigned short     u16;

__device__ __forceinline__ u32 smem_u32(const void* p) {
    u32 a;
    asm("{ .reg .u64 t; cvta.to.shared.u64 t, %1; cvt.u32.u64 %0, t; }" : "=r"(a) : "l"(p));
    return a;
}
__device__ __forceinline__ void cpasync16(u32 dst, const void* src) {
    asm volatile("cp.async.cg.shared.global [%0], [%1], 16;" :: "r"(dst), "l"(src));
}
__device__ __forceinline__ void cp_commit() {
    asm volatile("cp.async.commit_group;" ::: "memory");
}
template<int N> __device__ __forceinline__ void cp_wait() {
    asm volatile("cp.async.wait_group %0;" :: "n"(N) : "memory");
}
__device__ __forceinline__ void ldsm4(u32* r, u32 addr) {
    asm volatile("ldmatrix.sync.aligned.m8n8.x4.shared.b16 {%0,%1,%2,%3}, [%4];"
                 : "=r"(r[0]), "=r"(r[1]), "=r"(r[2]), "=r"(r[3]) : "r"(addr));
}
__device__ __forceinline__ void ldsm4t(u32* r, u32 addr) {
    asm volatile("ldmatrix.sync.aligned.m8n8.x4.trans.shared.b16 {%0,%1,%2,%3}, [%4];"
                 : "=r"(r[0]), "=r"(r[1]), "=r"(r[2]), "=r"(r[3]) : "r"(addr));
}
__device__ __forceinline__ void mma16816(float* c, const u32* a, u32 b0, u32 b1) {
    asm volatile(
        "mma.sync.aligned.m16n8k16.row.col.f32.f16.f16.f32 "
        "{%0,%1,%2,%3}, {%4,%5,%6,%7}, {%8,%9}, {%0,%1,%2,%3};"
        : "+f"(c[0]), "+f"(c[1]), "+f"(c[2]), "+f"(c[3])
        : "r"(a[0]), "r"(a[1]), "r"(a[2]), "r"(a[3]), "r"(b0), "r"(b1));
}
__device__ __forceinline__ u32 pack_h2(float e0, float e1) {
    u32 r;
    asm("cvt.rn.f16x2.f32 %0, %1, %2;" : "=r"(r) : "f"(e1), "f"(e0));  // e0 low, e1 high
    return r;
}

// ============================================================================
// Prep kernels
// ============================================================================
__global__ void prep_weights(const float* __restrict__ Wq0, const float* __restrict__ Wkv0,
                             const float* __restrict__ Wout0,
                             const float* __restrict__ Wq1, const float* __restrict__ Wkv1,
                             const float* __restrict__ Wout1,
                             __half* __restrict__ Wh)
{
    const int m = blockIdx.x;      // 0..7 : [q0,k0,v0,o0,q1,k1,v1,o1]
    const int slab = blockIdx.y;   // 0..7
    const float* W;
    int ld = 256, coff = 0;
    float scale = 1.0f;
    switch (m & 3) {
        case 0: W = (m < 4) ? Wq0 : Wq1; scale = 0.17677669529663687f; break;  // 32^-0.5
        case 1: W = (m < 4) ? Wkv0 : Wkv1; ld = 512; break;
        case 2: W = (m < 4) ? Wkv0 : Wkv1; ld = 512; coff = 256; break;
        default: W = (m < 4) ? Wout0 : Wout1; break;
    }
    __half* dh = Wh + (size_t)m * 65536;
    for (int e = threadIdx.x; e < 8192; e += 256) {
        int n = slab * 32 + (e >> 8);
        int k = e & 255;
        dh[n * 256 + k] = __float2half_rn(W[k * ld + coff + n] * scale);  // B[n][k]=W[k][n]
    }
}

__global__ void cvt_x_kernel(const float* __restrict__ x, __half* __restrict__ xh)
{
    size_t i = ((size_t)blockIdx.x * 256 + threadIdx.x) * 4;
    float4 v = *(const float4*)(x + i);
    u32 w0 = pack_h2(v.x, v.y);
    u32 w1 = pack_h2(v.z, v.w);
    *(uint2*)((u16*)xh + i) = make_uint2(w0, w1);
}

// ============================================================================
// QKV GEMM: 128m x 128n x 256k, fp16 single pass, 3-stage cp.async (as R7).
// ============================================================================
#define GS_ROWB   80
#define GS_PART   10240
#define GS_STAGE  20480
#define GS_SMEM   61440     // 3 stages

__global__ void __launch_bounds__(256)
gemm_qkv(const __half* __restrict__ Ah, const __half* __restrict__ Bbase,
         __half* __restrict__ Qh, __half* __restrict__ Kh, __half* __restrict__ Vh)
{
    extern __shared__ __align__(128) char smem[];
    const u32 sb = smem_u32(smem);
    const int t = threadIdx.x;
    const int bx = blockIdx.x;
    const int mat = bx >> 1;                 // 0=Q 1=K 2=V
    const int colBase = (bx & 1) << 7;
    const int rowBase = blockIdx.y << 7;

    const __half* Bh = Bbase + (size_t)mat * 65536;
    __half* Ch = (mat == 0) ? Qh : (mat == 1) ? Kh : Vh;

    float acc[4][4][4];
#pragma unroll
    for (int i = 0; i < 4; i++)
#pragma unroll
        for (int j = 0; j < 4; j++)
#pragma unroll
            for (int q = 0; q < 4; q++) acc[i][j][q] = 0.f;

    const int l = t & 31;
    const int wm = (t >> 5) >> 2;
    const int wn = (t >> 5) & 3;
    const int lr = t >> 2, lc = t & 3;
    const u32 lmOff = (u32)((l & 15) * GS_ROWB + (l >> 4) * 16);

    auto prefetch = [&](int kc) {
        const u32 stb = sb + (u32)(kc % 3) * GS_STAGE;
        const int kcol = kc * 32;
#pragma unroll
        for (int i = 0; i < 2; i++) {
            const int r = lr + i * 64;
            const u32 doff = (u32)(r * GS_ROWB + lc * 16);
            const size_t gA = (size_t)(rowBase + r) * 256 + kcol + lc * 8;
            const size_t gB = (size_t)(colBase + r) * 256 + kcol + lc * 8;
            cpasync16(stb + doff,           Ah + gA);
            cpasync16(stb + GS_PART + doff, Bh + gB);
        }
        cp_commit();
    };

    prefetch(0);
    prefetch(1);

    for (int kc = 0; kc < 8; kc++) {
        if (kc < 7) cp_wait<1>(); else cp_wait<0>();
        __syncthreads();
        if (kc < 6) prefetch(kc + 2);

        const u32 stb = sb + (u32)(kc % 3) * GS_STAGE;
#pragma unroll
        for (int ks = 0; ks < 2; ks++) {
            u32 ah[4][4];
#pragma unroll
            for (int mf = 0; mf < 4; mf++) {
                const u32 a = stb + (u32)((wm * 64 + mf * 16) * GS_ROWB + ks * 32) + lmOff;
                ldsm4(ah[mf], a);
            }
            u32 bh[2][4];
#pragma unroll
            for (int g = 0; g < 2; g++) {
                const u32 b = stb + GS_PART
                            + (u32)((wn * 32 + g * 16) * GS_ROWB + ks * 32) + lmOff;
                ldsm4(bh[g], b);
            }
#pragma unroll
            for (int mf = 0; mf < 4; mf++)
#pragma unroll
                for (int nf = 0; nf < 4; nf++)
                    mma16816(acc[mf][nf], ah[mf], bh[nf >> 1][nf & 1], bh[nf >> 1][(nf & 1) + 2]);
        }
        __syncthreads();
    }

    const int wm2 = (t >> 5) >> 2, wn2 = (t >> 5) & 3;
#pragma unroll
    for (int mf = 0; mf < 4; mf++) {
        const int m0 = rowBase + wm2 * 64 + mf * 16 + (l >> 2);
#pragma unroll
        for (int nf = 0; nf < 4; nf++) {
            const int col = colBase + wn2 * 32 + nf * 8 + 2 * (l & 3);
            const size_t i0 = (size_t)m0 * 256 + col;
            const size_t i1 = i0 + 8 * 256;
            *(u32*)((u16*)Ch + i0) = pack_h2(acc[mf][nf][0], acc[mf][nf][1]);
            *(u32*)((u16*)Ch + i1) = pack_h2(acc[mf][nf][2], acc[mf][nf][3]);
        }
    }
}

// ============================================================================
// Fused attention + out-projection. Block = one sequence (128 tokens), 512 thr.
//  - Q/K/V full 128x256 fp16 tiles in smem, 528-B row stride (conflict-free).
//  - 4 iterations x 2 heads in parallel (warps 0-7 / 8-15); warp owns 16 rows.
//  - O_h overwrites Q's head-h column slice (dead after its S) — no syncs.
//  - Out-proj: O(=Q tile) @ Wout streamed from L2, k=16 chunks, double-buffered.
// ============================================================================
#define AO_ROWB  528
#define AO_TILE  67584            // 128 * 528
#define AO_Q     0
#define AO_K     67584
#define AO_V     135168
#define AO_W     202752
#define AO_WROWB 48
#define AO_WST   12288            // 256 * 48
#define AO_SMEM  227328           // 3 tiles + 2 W stages

template<bool ACCUM>
__global__ void __launch_bounds__(512)
attn_out(const __half* __restrict__ Qg, const __half* __restrict__ Kg,
         const __half* __restrict__ Vg, const __half* __restrict__ Wm,
         const float* __restrict__ bias, float* __restrict__ out, int axis)
{
    extern __shared__ __align__(128) char smem[];
    const u32 sb = smem_u32(smem);
    const int t = threadIdx.x;
    const int l = t & 31;
    const int w = t >> 5;

    const int s = blockIdx.x;
    int tokBase, tokStride;
    if (axis == 0) { int b = s >> 7, ww = s & 127; tokBase = b * 16384 + ww; tokStride = 128; }
    else           { tokBase = s * 128; tokStride = 1; }

    // ---- load Q, K, V full tiles ----
    {
        const __half* srcs[3] = { Qg, Kg, Vg };
#pragma unroll
        for (int mtx = 0; mtx < 3; mtx++) {
            const u16* src = (const u16*)srcs[mtx];
            const u32 base = sb + mtx * AO_TILE;
#pragma unroll
            for (int i = 0; i < 8; i++) {
                const int idx = t + i * 512;
                const int row = idx >> 5, seg = idx & 31;
                const size_t g = (size_t)(tokBase + row * tokStride) * 256 + seg * 8;
                cpasync16(base + row * AO_ROWB + seg * 16, src + g);
            }
        }
        cp_commit();
        cp_wait<0>();
        __syncthreads();
    }

    const u32 lmT = (u32)((l & 15) * AO_ROWB + (l >> 4) * 16);
    const int hw = w >> 3;          // head-of-pair
    const int ws = w & 7;           // 16-row strip within sequence

    // ---- attention: 4 iterations x 2 heads ----
#pragma unroll 1
    for (int it = 0; it < 4; it++) {
        const int h = it * 2 + hw;
        const u32 colB = (u32)(h * 64);         // byte offset of head slice

        float sv[16][4];
#pragma unroll
        for (int nf = 0; nf < 16; nf++)
#pragma unroll
            for (int q = 0; q < 4; q++) sv[nf][q] = 0.f;

#pragma unroll
        for (int kc = 0; kc < 2; kc++) {
            u32 aq[4];
            ldsm4(aq, sb + AO_Q + (u32)(ws * 16) * AO_ROWB + colB + kc * 32 + lmT);
#pragma unroll
            for (int gp = 0; gp < 4; gp++) {
                u32 kh4[2][4];
#pragma unroll
                for (int gi = 0; gi < 2; gi++)
                    ldsm4(kh4[gi], sb + AO_K + (u32)((gp * 2 + gi) * 16) * AO_ROWB
                                   + colB + kc * 32 + lmT);
#pragma unroll
                for (int gi = 0; gi < 2; gi++)
#pragma unroll
                    for (int j = 0; j < 2; j++)
                        mma16816(sv[(gp * 2 + gi) * 2 + j], aq, kh4[gi][j], kh4[gi][j + 2]);
            }
        }

        // softmax (rows fully in-warp: quad shuffles)
        float mx0 = -1e30f, mx1 = -1e30f;
#pragma unroll
        for (int nf = 0; nf < 16; nf++) {
            mx0 = fmaxf(mx0, fmaxf(sv[nf][0], sv[nf][1]));
            mx1 = fmaxf(mx1, fmaxf(sv[nf][2], sv[nf][3]));
        }
        mx0 = fmaxf(mx0, __shfl_xor_sync(0xffffffffu, mx0, 1));
        mx0 = fmaxf(mx0, __shfl_xor_sync(0xffffffffu, mx0, 2));
        mx1 = fmaxf(mx1, __shfl_xor_sync(0xffffffffu, mx1, 1));
        mx1 = fmaxf(mx1, __shfl_xor_sync(0xffffffffu, mx1, 2));

        float sum0 = 0.f, sum1 = 0.f;
#pragma unroll
        for (int nf = 0; nf < 16; nf++) {
            sv[nf][0] = __expf(sv[nf][0] - mx0);
            sv[nf][1] = __expf(sv[nf][1] - mx0);
            sv[nf][2] = __expf(sv[nf][2] - mx1);
            sv[nf][3] = __expf(sv[nf][3] - mx1);
            sum0 += sv[nf][0] + sv[nf][1];
            sum1 += sv[nf][2] + sv[nf][3];
        }
        sum0 += __shfl_xor_sync(0xffffffffu, sum0, 1);
        sum0 += __shfl_xor_sync(0xffffffffu, sum0, 2);
        sum1 += __shfl_xor_sync(0xffffffffu, sum1, 1);
        sum1 += __shfl_xor_sync(0xffffffffu, sum1, 2);
        const float inv0 = 1.0f / sum0;
        const float inv1 = 1.0f / sum1;

        // O = P V
        float ao[4][4];
#pragma unroll
        for (int nf = 0; nf < 4; nf++)
#pragma unroll
            for (int q = 0; q < 4; q++) ao[nf][q] = 0.f;

#pragma unroll
        for (int jc = 0; jc < 8; jc++) {
            u32 ph[4];
            ph[0] = pack_h2(sv[2 * jc][0],     sv[2 * jc][1]);
            ph[1] = pack_h2(sv[2 * jc][2],     sv[2 * jc][3]);
            ph[2] = pack_h2(sv[2 * jc + 1][0], sv[2 * jc + 1][1]);
            ph[3] = pack_h2(sv[2 * jc + 1][2], sv[2 * jc + 1][3]);
            u32 vh4[2][4];
#pragma unroll
            for (int eg = 0; eg < 2; eg++)
                ldsm4t(vh4[eg], sb + AO_V + (u32)(jc * 16) * AO_ROWB + colB + eg * 32 + lmT);
#pragma unroll
            for (int eg = 0; eg < 2; eg++)
#pragma unroll
                for (int j = 0; j < 2; j++)
                    mma16816(ao[eg * 2 + j], ph, vh4[eg][j * 2], vh4[eg][j * 2 + 1]);
        }

        // normalize + write O into Q tile's head-h slice (warp-local rows)
        const int row0 = ws * 16 + (l >> 2);
        const int row1 = row0 + 8;
#pragma unroll
        for (int nf = 0; nf < 4; nf++) {
            const u32 colO = colB + (u32)((nf * 8 + 2 * (l & 3)) * 2);
            *(u32*)(smem + AO_Q + row0 * AO_ROWB + colO) = pack_h2(ao[nf][0] * inv0, ao[nf][1] * inv0);
            *(u32*)(smem + AO_Q + row1 * AO_ROWB + colO) = pack_h2(ao[nf][2] * inv1, ao[nf][3] * inv1);
        }
    }

    __syncthreads();   // O tile complete before cross-warp out-projection reads

    // ---- out-projection: O(128x256) @ Wout^T, k=16 chunks, double-buffered ----
    const int wm = w >> 3;          // 0..1  (64-row half)
    const int wn = w & 7;           // 0..7  (32-col group)
    const u32 lmW = (u32)((l & 15) * AO_WROWB + (l >> 4) * 16);

    float acc[4][4][4];
#pragma unroll
    for (int i = 0; i < 4; i++)
#pragma unroll
        for (int j = 0; j < 4; j++)
#pragma unroll
            for (int q = 0; q < 4; q++) acc[i][j][q] = 0.f;

    auto prefW = [&](int kc) {
        const int row = t >> 1, seg = t & 1;
        const size_t g = (size_t)row * 256 + kc * 16 + seg * 8;
        cpasync16(sb + AO_W + (u32)(kc & 1) * AO_WST + row * AO_WROWB + seg * 16,
                  (const u16*)Wm + g);
        cp_commit();
    };

    prefW(0);
    prefW(1);

    for (int kc = 0; kc < 16; kc++) {
        if (kc < 15) cp_wait<1>(); else cp_wait<0>();
        __syncthreads();

        const u32 stb = sb + AO_W + (u32)(kc & 1) * AO_WST;
        u32 af[4][4];
#pragma unroll
        for (int mf = 0; mf < 4; mf++)
            ldsm4(af[mf], sb + AO_Q + (u32)(wm * 64 + mf * 16) * AO_ROWB + kc * 32 + lmT);
        u32 bf[2][4];
#pragma unroll
        for (int gi = 0; gi < 2; gi++)
            ldsm4(bf[gi], stb + (u32)(wn * 32 + gi * 16) * AO_WROWB + lmW);
#pragma unroll
        for (int mf = 0; mf < 4; mf++)
#pragma unroll
            for (int nf = 0; nf < 4; nf++)
                mma16816(acc[mf][nf], af[mf], bf[nf >> 1][nf & 1], bf[nf >> 1][(nf & 1) + 2]);

        __syncthreads();
        if (kc < 14) prefW(kc + 2);
    }

    // ---- epilogue: bias (+accum) -> f32 out ----
#pragma unroll
    for (int mf = 0; mf < 4; mf++) {
        const int m0 = wm * 64 + mf * 16 + (l >> 2);
        const size_t tok0 = (size_t)(tokBase + m0 * tokStride) * 256;
        const size_t tok1 = (size_t)(tokBase + (m0 + 8) * tokStride) * 256;
#pragma unroll
        for (int nf = 0; nf < 4; nf++) {
            const int col = wn * 32 + nf * 8 + 2 * (l & 3);
            float2 b = *(const float2*)(bias + col);
            float2 v0 = make_float2(acc[mf][nf][0] + b.x, acc[mf][nf][1] + b.y);
            float2 v1 = make_float2(acc[mf][nf][2] + b.x, acc[mf][nf][3] + b.y);
            float* p0 = out + tok0 + col;
            float* p1 = out + tok1 + col;
            if (ACCUM) {
                float2 c0 = *(float2*)p0, c1 = *(float2*)p1;
                v0.x += c0.x; v0.y += c0.y; v1.x += c1.x; v1.y += c1.y;
            }
            *(float2*)p0 = v0;
            *(float2*)p1 = v1;
        }
    }
}

// ============================================================================
// Host launcher
// ============================================================================
extern "C" void kernel_launch(void* const* d_in, const int* in_sizes, int n_in,
                              void* d_out, int out_size)
{
    (void)in_sizes; (void)n_in; (void)out_size;
    const float* x     = (const float*)d_in[0];
    const float* Wq0   = (const float*)d_in[1];
    const float* Wkv0  = (const float*)d_in[2];
    const float* Wout0 = (const float*)d_in[3];
    const float* bout0 = (const float*)d_in[4];
    const float* Wq1   = (const float*)d_in[5];
    const float* Wkv1  = (const float*)d_in[6];
    const float* Wout1 = (const float*)d_in[7];
    const float* bout1 = (const float*)d_in[8];
    float* out = (float*)d_out;

    __half *xh, *Qhb, *Khb, *Vhb, *Wh;
    cudaGetSymbolAddress((void**)&xh,  g_xh);
    cudaGetSymbolAddress((void**)&Qhb, g_Qh);
    cudaGetSymbolAddress((void**)&Khb, g_Kh);
    cudaGetSymbolAddress((void**)&Vhb, g_Vh);
    cudaGetSymbolAddress((void**)&Wh,  g_Wh);

    cudaFuncSetAttribute(gemm_qkv,
                         cudaFuncAttributeMaxDynamicSharedMemorySize, GS_SMEM);
    cudaFuncSetAttribute(attn_out<false>,
                         cudaFuncAttributeMaxDynamicSharedMemorySize, AO_SMEM);
    cudaFuncSetAttribute(attn_out<true>,
                         cudaFuncAttributeMaxDynamicSharedMemorySize, AO_SMEM);

    const dim3 gq(6, 1024);    // fused QKV: (mat*2 + ntile, m tiles)

    prep_weights<<<dim3(8, 8), 256>>>(Wq0, Wkv0, Wout0, Wq1, Wkv1, Wout1, Wh);
    cvt_x_kernel<<<32768, 256>>>(x, xh);

    // ---- axis 0 ----
    gemm_qkv<<<gq, 256, GS_SMEM>>>(xh, Wh, Qhb, Khb, Vhb);
    attn_out<false><<<1024, 512, AO_SMEM>>>(Qhb, Khb, Vhb, Wh + 3u * 65536, bout0, out, 0);

    // ---- axis 1 ----
    gemm_qkv<<<gq, 256, GS_SMEM>>>(xh, Wh + 4u * 65536, Qhb, Khb, Vhb);
    attn_out<true><<<1024, 512, AO_SMEM>>>(Qhb, Khb, Vhb, Wh + 7u * 65536, bout1, out, 1);
}

// round 9
// speedup vs baseline: 1.1000x; 1.1000x over previous
#include <cuda_runtime.h>
#include <cuda_fp16.h>

// ============================================================================
// AxialAttention — pure fp16 HMMA (R7 kernels) + cross-axis launch fusion.
// 5 launches: prep, cvt, qkv(both axes), attn(both axes), out-proj(combined).
// ============================================================================

#define NTOK 131072          // 8*128*128 tokens

// ---- scratch (device globals: allocation-guard safe) ----
__device__ __half g_xh[NTOK * 256];
__device__ __half g_Q0[NTOK * 256];
__device__ __half g_K0[NTOK * 256];
__device__ __half g_V0[NTOK * 256];
__device__ __half g_Q1[NTOK * 256];
__device__ __half g_K1[NTOK * 256];
__device__ __half g_V1[NTOK * 256];
__device__ __half g_O0[NTOK * 256];
__device__ __half g_O1[NTOK * 256];
__device__ __half g_Wh[8 * 65536];     // 8 mats, [n][k] 256x256

typedef unsigned long long ull;
typedef unsigned int       u32;
typedef unsigned short     u16;

__device__ __forceinline__ u32 smem_u32(const void* p) {
    u32 a;
    asm("{ .reg .u64 t; cvta.to.shared.u64 t, %1; cvt.u32.u64 %0, t; }" : "=r"(a) : "l"(p));
    return a;
}
__device__ __forceinline__ void cpasync16(u32 dst, const void* src) {
    asm volatile("cp.async.cg.shared.global [%0], [%1], 16;" :: "r"(dst), "l"(src));
}
__device__ __forceinline__ void cp_commit() {
    asm volatile("cp.async.commit_group;" ::: "memory");
}
template<int N> __device__ __forceinline__ void cp_wait() {
    asm volatile("cp.async.wait_group %0;" :: "n"(N) : "memory");
}
__device__ __forceinline__ void ldsm4(u32* r, u32 addr) {
    asm volatile("ldmatrix.sync.aligned.m8n8.x4.shared.b16 {%0,%1,%2,%3}, [%4];"
                 : "=r"(r[0]), "=r"(r[1]), "=r"(r[2]), "=r"(r[3]) : "r"(addr));
}
__device__ __forceinline__ void ldsm4t(u32* r, u32 addr) {
    asm volatile("ldmatrix.sync.aligned.m8n8.x4.trans.shared.b16 {%0,%1,%2,%3}, [%4];"
                 : "=r"(r[0]), "=r"(r[1]), "=r"(r[2]), "=r"(r[3]) : "r"(addr));
}
__device__ __forceinline__ void mma16816(float* c, const u32* a, u32 b0, u32 b1) {
    asm volatile(
        "mma.sync.aligned.m16n8k16.row.col.f32.f16.f16.f32 "
        "{%0,%1,%2,%3}, {%4,%5,%6,%7}, {%8,%9}, {%0,%1,%2,%3};"
        : "+f"(c[0]), "+f"(c[1]), "+f"(c[2]), "+f"(c[3])
        : "r"(a[0]), "r"(a[1]), "r"(a[2]), "r"(a[3]), "r"(b0), "r"(b1));
}
__device__ __forceinline__ u32 pack_h2(float e0, float e1) {
    u32 r;
    asm("cvt.rn.f16x2.f32 %0, %1, %2;" : "=r"(r) : "f"(e1), "f"(e0));  // e0 low, e1 high
    return r;
}

// ============================================================================
// Prep kernels
// ============================================================================
__global__ void prep_weights(const float* __restrict__ Wq0, const float* __restrict__ Wkv0,
                             const float* __restrict__ Wout0,
                             const float* __restrict__ Wq1, const float* __restrict__ Wkv1,
                             const float* __restrict__ Wout1,
                             __half* __restrict__ Wh)
{
    const int m = blockIdx.x;      // 0..7 : [q0,k0,v0,o0,q1,k1,v1,o1]
    const int slab = blockIdx.y;   // 0..7
    const float* W;
    int ld = 256, coff = 0;
    float scale = 1.0f;
    switch (m & 3) {
        case 0: W = (m < 4) ? Wq0 : Wq1; scale = 0.17677669529663687f; break;  // 32^-0.5
        case 1: W = (m < 4) ? Wkv0 : Wkv1; ld = 512; break;
        case 2: W = (m < 4) ? Wkv0 : Wkv1; ld = 512; coff = 256; break;
        default: W = (m < 4) ? Wout0 : Wout1; break;
    }
    __half* dh = Wh + (size_t)m * 65536;
    for (int e = threadIdx.x; e < 8192; e += 256) {
        int n = slab * 32 + (e >> 8);
        int k = e & 255;
        dh[n * 256 + k] = __float2half_rn(W[k * ld + coff + n] * scale);  // B[n][k]=W[k][n]
    }
}

__global__ void cvt_x_kernel(const float* __restrict__ x, __half* __restrict__ xh)
{
    size_t i = ((size_t)blockIdx.x * 256 + threadIdx.x) * 4;
    float4 v = *(const float4*)(x + i);
    u32 w0 = pack_h2(v.x, v.y);
    u32 w1 = pack_h2(v.z, v.w);
    *(uint2*)((u16*)xh + i) = make_uint2(w0, w1);
}

// ============================================================================
// GEMM mainloop: 128m x 128n x 256k, fp16 single pass, 3-stage cp.async.
// Does NOT reset acc — callable twice for the combined out-projection.
// ============================================================================
#define GS_ROWB   80
#define GS_PART   10240
#define GS_STAGE  20480
#define GS_SMEM   61440     // 3 stages

__device__ __forceinline__ void gemm_mainloop(
    u32 sb, const __half* __restrict__ Ah, const __half* __restrict__ Bh,
    int rowBase, int colBase, int t, float acc[4][4][4])
{
    const int l = t & 31;
    const int wm = (t >> 5) >> 2;
    const int wn = (t >> 5) & 3;
    const int lr = t >> 2, lc = t & 3;
    const u32 lmOff = (u32)((l & 15) * GS_ROWB + (l >> 4) * 16);

    auto prefetch = [&](int kc) {
        const u32 stb = sb + (u32)(kc % 3) * GS_STAGE;
        const int kcol = kc * 32;
#pragma unroll
        for (int i = 0; i < 2; i++) {
            const int r = lr + i * 64;
            const u32 doff = (u32)(r * GS_ROWB + lc * 16);
            const size_t gA = (size_t)(rowBase + r) * 256 + kcol + lc * 8;
            const size_t gB = (size_t)(colBase + r) * 256 + kcol + lc * 8;
            cpasync16(stb + doff,           Ah + gA);
            cpasync16(stb + GS_PART + doff, Bh + gB);
        }
        cp_commit();
    };

    prefetch(0);
    prefetch(1);

    for (int kc = 0; kc < 8; kc++) {
        if (kc < 7) cp_wait<1>(); else cp_wait<0>();
        __syncthreads();
        if (kc < 6) prefetch(kc + 2);

        const u32 stb = sb + (u32)(kc % 3) * GS_STAGE;
#pragma unroll
        for (int ks = 0; ks < 2; ks++) {
            u32 ah[4][4];
#pragma unroll
            for (int mf = 0; mf < 4; mf++) {
                const u32 a = stb + (u32)((wm * 64 + mf * 16) * GS_ROWB + ks * 32) + lmOff;
                ldsm4(ah[mf], a);
            }
            u32 bh[2][4];
#pragma unroll
            for (int g = 0; g < 2; g++) {
                const u32 b = stb + GS_PART
                            + (u32)((wn * 32 + g * 16) * GS_ROWB + ks * 32) + lmOff;
                ldsm4(bh[g], b);
            }
#pragma unroll
            for (int mf = 0; mf < 4; mf++)
#pragma unroll
                for (int nf = 0; nf < 4; nf++)
                    mma16816(acc[mf][nf], ah[mf], bh[nf >> 1][nf & 1], bh[nf >> 1][(nf & 1) + 2]);
        }
        __syncthreads();
    }
}

// ---- QKV projection, BOTH axes: grid (12, 1024) ----
// bx>>1 = mat index 0..5 = [q0,k0,v0,q1,k1,v1]; bx&1 = n-tile.
__global__ void __launch_bounds__(256)
gemm_qkv6(const __half* __restrict__ Ah, const __half* __restrict__ Wh,
          __half* __restrict__ Q0, __half* __restrict__ K0, __half* __restrict__ V0,
          __half* __restrict__ Q1, __half* __restrict__ K1, __half* __restrict__ V1)
{
    extern __shared__ __align__(128) char smem[];
    const u32 sb = smem_u32(smem);
    const int t = threadIdx.x;
    const int bx = blockIdx.x;
    const int mat = bx >> 1;                 // 0..5
    const int colBase = (bx & 1) << 7;
    const int rowBase = blockIdx.y << 7;

    // weight slot: mats 0-2 -> Wh[0..2]; mats 3-5 -> Wh[4..6]
    const int wslot = (mat < 3) ? mat : (mat + 1);
    const __half* Bh = Wh + (size_t)wslot * 65536;
    __half* Ch;
    switch (mat) {
        case 0: Ch = Q0; break;
        case 1: Ch = K0; break;
        case 2: Ch = V0; break;
        case 3: Ch = Q1; break;
        case 4: Ch = K1; break;
        default: Ch = V1; break;
    }

    float acc[4][4][4];
#pragma unroll
    for (int i = 0; i < 4; i++)
#pragma unroll
        for (int j = 0; j < 4; j++)
#pragma unroll
            for (int q = 0; q < 4; q++) acc[i][j][q] = 0.f;

    gemm_mainloop(sb, Ah, Bh, rowBase, colBase, t, acc);

    const int l = t & 31;
    const int wm = (t >> 5) >> 2, wn = (t >> 5) & 3;
#pragma unroll
    for (int mf = 0; mf < 4; mf++) {
        const int m0 = rowBase + wm * 64 + mf * 16 + (l >> 2);
#pragma unroll
        for (int nf = 0; nf < 4; nf++) {
            const int col = colBase + wn * 32 + nf * 8 + 2 * (l & 3);
            const size_t i0 = (size_t)m0 * 256 + col;
            const size_t i1 = i0 + 8 * 256;
            *(u32*)((u16*)Ch + i0) = pack_h2(acc[mf][nf][0], acc[mf][nf][1]);
            *(u32*)((u16*)Ch + i1) = pack_h2(acc[mf][nf][2], acc[mf][nf][3]);
        }
    }
}

// ---- combined out-projection: out = O0 @ W3^T + O1 @ W7^T + b0 + b1 ----
__global__ void __launch_bounds__(256)
gemm_out2(const __half* __restrict__ O0, const __half* __restrict__ O1,
          const __half* __restrict__ Wh,
          const float* __restrict__ b0, const float* __restrict__ b1,
          float* __restrict__ C)
{
    extern __shared__ __align__(128) char smem[];
    const u32 sb = smem_u32(smem);
    const int t = threadIdx.x;
    const int rowBase = blockIdx.y << 7;
    const int colBase = blockIdx.x << 7;

    float acc[4][4][4];
#pragma unroll
    for (int i = 0; i < 4; i++)
#pragma unroll
        for (int j = 0; j < 4; j++)
#pragma unroll
            for (int q = 0; q < 4; q++) acc[i][j][q] = 0.f;

    gemm_mainloop(sb, O0, Wh + 3u * 65536, rowBase, colBase, t, acc);
    __syncthreads();
    gemm_mainloop(sb, O1, Wh + 7u * 65536, rowBase, colBase, t, acc);

    const int l = t & 31;
    const int wm = (t >> 5) >> 2, wn = (t >> 5) & 3;
#pragma unroll
    for (int mf = 0; mf < 4; mf++) {
        const int m0 = rowBase + wm * 64 + mf * 16 + (l >> 2);
#pragma unroll
        for (int nf = 0; nf < 4; nf++) {
            const int col = colBase + wn * 32 + nf * 8 + 2 * (l & 3);
            float2 ba = *(const float2*)(b0 + col);
            float2 bb = *(const float2*)(b1 + col);
            float2 v0 = make_float2(acc[mf][nf][0] + ba.x + bb.x,
                                    acc[mf][nf][1] + ba.y + bb.y);
            float2 v1 = make_float2(acc[mf][nf][2] + ba.x + bb.x,
                                    acc[mf][nf][3] + ba.y + bb.y);
            float* p0 = C + (size_t)m0 * 256 + col;
            float* p1 = p0 + 8 * 256;
            *(float2*)p0 = v0;
            *(float2*)p1 = v1;
        }
    }
}

// ============================================================================
// HMMA attention, BOTH axes: grid (2048, 8). bx>>10 = axis, bx&1023 = sequence.
// Warp w owns query rows w*16..+15 (quad-only softmax).
// ============================================================================
#define AT_ROWB 80
#define AT_TILE 10240
#define AT_SMEM (3 * AT_TILE)   // 30720

__global__ void __launch_bounds__(256, 2)
attn_mma2(const __half* __restrict__ Q0g, const __half* __restrict__ K0g,
          const __half* __restrict__ V0g,
          const __half* __restrict__ Q1g, const __half* __restrict__ K1g,
          const __half* __restrict__ V1g,
          __half* __restrict__ O0g, __half* __restrict__ O1g)
{
    extern __shared__ __align__(128) char smem[];
    const u32 sb = smem_u32(smem);
    const int t = threadIdx.x;
    const int l = t & 31;
    const int w = t >> 5;

    const int axis = blockIdx.x >> 10;
    const int s = blockIdx.x & 1023;
    const int head = blockIdx.y;
    int tokBase, tokStride;
    if (axis == 0) { int b = s >> 7, ww = s & 127; tokBase = b * 16384 + ww; tokStride = 128; }
    else           { tokBase = s * 128; tokStride = 1; }
    const int chanOff = head * 32;

    const __half* Qh = axis ? Q1g : Q0g;
    const __half* Kh = axis ? K1g : K0g;
    const __half* Vh = axis ? V1g : V0g;
    __half*       Oh = axis ? O1g : O0g;

    // ---- load 3 tiles (cp.async, one shot) ----
    {
        const __half* srcs[3] = { Qh, Kh, Vh };
#pragma unroll
        for (int tile = 0; tile < 3; tile++) {
            const u16* src = (const u16*)srcs[tile];
#pragma unroll
            for (int i = 0; i < 2; i++) {
                const int c = t + i * 256;
                const int row = c >> 2, cg = c & 3;
                const size_t g = (size_t)(tokBase + row * tokStride) * 256 + chanOff + cg * 8;
                cpasync16(sb + tile * AT_TILE + row * AT_ROWB + cg * 16, src + g);
            }
        }
        cp_commit();
        cp_wait<0>();
        __syncthreads();
    }

    const u32 lmOff = (u32)((l & 15) * AT_ROWB + (l >> 4) * 16);

    // ---- S = Q K^T, warp strip rows w*16..+15, full 128 cols ----
    float sv[16][4];
#pragma unroll
    for (int nf = 0; nf < 16; nf++)
#pragma unroll
        for (int q = 0; q < 4; q++) sv[nf][q] = 0.f;

#pragma unroll
    for (int kc = 0; kc < 2; kc++) {
        u32 aq[4];
        const u32 qa = sb + (u32)(w * 16 * AT_ROWB + kc * 32) + lmOff;
        ldsm4(aq, qa);
#pragma unroll
        for (int gp = 0; gp < 4; gp++) {
            u32 kh4[2][4];
#pragma unroll
            for (int gi = 0; gi < 2; gi++) {
                const int g = gp * 2 + gi;
                const u32 ka = sb + AT_TILE + (u32)(g * 16 * AT_ROWB + kc * 32) + lmOff;
                ldsm4(kh4[gi], ka);
            }
#pragma unroll
            for (int gi = 0; gi < 2; gi++)
#pragma unroll
                for (int j = 0; j < 2; j++)
                    mma16816(sv[(gp * 2 + gi) * 2 + j], aq, kh4[gi][j], kh4[gi][j + 2]);
        }
    }

    // ---- softmax (rows fully in-warp: quad shuffles only) ----
    float mx0 = -1e30f, mx1 = -1e30f;
#pragma unroll
    for (int nf = 0; nf < 16; nf++) {
        mx0 = fmaxf(mx0, fmaxf(sv[nf][0], sv[nf][1]));
        mx1 = fmaxf(mx1, fmaxf(sv[nf][2], sv[nf][3]));
    }
    mx0 = fmaxf(mx0, __shfl_xor_sync(0xffffffffu, mx0, 1));
    mx0 = fmaxf(mx0, __shfl_xor_sync(0xffffffffu, mx0, 2));
    mx1 = fmaxf(mx1, __shfl_xor_sync(0xffffffffu, mx1, 1));
    mx1 = fmaxf(mx1, __shfl_xor_sync(0xffffffffu, mx1, 2));

    float sum0 = 0.f, sum1 = 0.f;
#pragma unroll
    for (int nf = 0; nf < 16; nf++) {
        sv[nf][0] = __expf(sv[nf][0] - mx0);
        sv[nf][1] = __expf(sv[nf][1] - mx0);
        sv[nf][2] = __expf(sv[nf][2] - mx1);
        sv[nf][3] = __expf(sv[nf][3] - mx1);
        sum0 += sv[nf][0] + sv[nf][1];
        sum1 += sv[nf][2] + sv[nf][3];
    }
    sum0 += __shfl_xor_sync(0xffffffffu, sum0, 1);
    sum0 += __shfl_xor_sync(0xffffffffu, sum0, 2);
    sum1 += __shfl_xor_sync(0xffffffffu, sum1, 1);
    sum1 += __shfl_xor_sync(0xffffffffu, sum1, 2);
    const float inv0 = 1.0f / sum0;
    const float inv1 = 1.0f / sum1;

    // ---- O = P V, P frags packed fp16 in-register ----
    float ao[4][4];
#pragma unroll
    for (int nf = 0; nf < 4; nf++)
#pragma unroll
        for (int q = 0; q < 4; q++) ao[nf][q] = 0.f;

#pragma unroll
    for (int jc = 0; jc < 8; jc++) {
        u32 ph[4];
        ph[0] = pack_h2(sv[2 * jc][0],     sv[2 * jc][1]);
        ph[1] = pack_h2(sv[2 * jc][2],     sv[2 * jc][3]);
        ph[2] = pack_h2(sv[2 * jc + 1][0], sv[2 * jc + 1][1]);
        ph[3] = pack_h2(sv[2 * jc + 1][2], sv[2 * jc + 1][3]);
        u32 vh4[2][4];
#pragma unroll
        for (int eg = 0; eg < 2; eg++) {
            const u32 va = sb + 2 * AT_TILE + (u32)(jc * 16 * AT_ROWB + eg * 32) + lmOff;
            ldsm4t(vh4[eg], va);
        }
#pragma unroll
        for (int eg = 0; eg < 2; eg++)
#pragma unroll
            for (int j = 0; j < 2; j++)
                mma16816(ao[eg * 2 + j], ph, vh4[eg][j * 2], vh4[eg][j * 2 + 1]);
    }

    // ---- normalize + write fp16 ----
    const int row0 = w * 16 + (l >> 2);
    const int row1 = row0 + 8;
    const size_t tok0 = (size_t)(tokBase + row0 * tokStride) * 256;
    const size_t tok1 = (size_t)(tokBase + row1 * tokStride) * 256;
#pragma unroll
    for (int nf = 0; nf < 4; nf++) {
        const int col = chanOff + nf * 8 + 2 * (l & 3);
        *(u32*)((u16*)Oh + tok0 + col) = pack_h2(ao[nf][0] * inv0, ao[nf][1] * inv0);
        *(u32*)((u16*)Oh + tok1 + col) = pack_h2(ao[nf][2] * inv1, ao[nf][3] * inv1);
    }
}

// ============================================================================
// Host launcher
// ============================================================================
extern "C" void kernel_launch(void* const* d_in, const int* in_sizes, int n_in,
                              void* d_out, int out_size)
{
    (void)in_sizes; (void)n_in; (void)out_size;
    const float* x     = (const float*)d_in[0];
    const float* Wq0   = (const float*)d_in[1];
    const float* Wkv0  = (const float*)d_in[2];
    const float* Wout0 = (const float*)d_in[3];
    const float* bout0 = (const float*)d_in[4];
    const float* Wq1   = (const float*)d_in[5];
    const float* Wkv1  = (const float*)d_in[6];
    const float* Wout1 = (const float*)d_in[7];
    const float* bout1 = (const float*)d_in[8];
    float* out = (float*)d_out;

    __half *xh, *Q0, *K0, *V0, *Q1, *K1, *V1, *O0, *O1, *Wh;
    cudaGetSymbolAddress((void**)&xh, g_xh);
    cudaGetSymbolAddress((void**)&Q0, g_Q0);
    cudaGetSymbolAddress((void**)&K0, g_K0);
    cudaGetSymbolAddress((void**)&V0, g_V0);
    cudaGetSymbolAddress((void**)&Q1, g_Q1);
    cudaGetSymbolAddress((void**)&K1, g_K1);
    cudaGetSymbolAddress((void**)&V1, g_V1);
    cudaGetSymbolAddress((void**)&O0, g_O0);
    cudaGetSymbolAddress((void**)&O1, g_O1);
    cudaGetSymbolAddress((void**)&Wh, g_Wh);

    cudaFuncSetAttribute(gemm_qkv6,
                         cudaFuncAttributeMaxDynamicSharedMemorySize, GS_SMEM);
    cudaFuncSetAttribute(gemm_out2,
                         cudaFuncAttributeMaxDynamicSharedMemorySize, GS_SMEM);
    cudaFuncSetAttribute(attn_mma2,
                         cudaFuncAttributeMaxDynamicSharedMemorySize, AT_SMEM);

    prep_weights<<<dim3(8, 8), 256>>>(Wq0, Wkv0, Wout0, Wq1, Wkv1, Wout1, Wh);
    cvt_x_kernel<<<32768, 256>>>(x, xh);

    gemm_qkv6<<<dim3(12, 1024), 256, GS_SMEM>>>(xh, Wh, Q0, K0, V0, Q1, K1, V1);
    attn_mma2<<<dim3(2048, 8), 256, AT_SMEM>>>(Q0, K0, V0, Q1, K1, V1, O0, O1);
    gemm_out2<<<dim3(2, 1024), 256, GS_SMEM>>>(O0, O1, Wh, bout0, bout1, out);
}